// round 11
// baseline (speedup 1.0000x reference)
#include <cuda_runtime.h>
#include <cstdint>

// ---------------- problem constants ----------------
#define NN 50000
#define EE 640000
#define ETOT (EE + NN)          // edges + self loops = 690000
#define DH 128                   // hidden dim
#define DF 512                   // ffn dim
#define NG 128                   // num graphs
#define NCLS 10
#define NEG_SLOPE 0.2f
#define MAXD 96                  // padded CSR row width (deg ~ Poisson(12.8)+1)

// ---------------- device scratch (no allocation allowed) ----------------
__device__ float g_hT[NN * DH];     // GEMM output
__device__ float g_bufA[NN * DH];   // layer output ping
__device__ float g_bufB[NN * DH];   // layer output pong
__device__ float g_asrc[NN];
__device__ float g_adst[NN];
__device__ int   g_fill[NN];
__device__ int   g_csr2[NN * MAXD];
__device__ float g_pooled[NG * DH];
__device__ int   g_cnt[NG];

__device__ __forceinline__ int clamp_id(int v) {
    v = (v < 0) ? 0 : v;
    return (v >= NN) ? (NN - 1) : v;
}

// ---------------- no-op (ncu launch-index steering) ----------------
__global__ void noop_kernel() {}

// ---------------- init (grid covers NN >= NG*DH) ----------------
__global__ void zero_kernel() {
    int i = blockIdx.x * blockDim.x + threadIdx.x;
    if (i < NN) g_fill[i] = 0;
    if (i < NG * DH) g_pooled[i] = 0.f;
    if (i < NG) g_cnt[i] = 0;
}

// ---------------- padded-CSR scatter (by dst) + graph counts ------------
__global__ void scatter_kernel(const int* __restrict__ ei,
                               const int* __restrict__ batch) {
    int e = blockIdx.x * blockDim.x + threadIdx.x;
    if (e >= ETOT) return;
    int s, d;
    if (e < EE) { s = clamp_id(ei[e]); d = clamp_id(ei[EE + e]); }
    else        { s = e - EE;          d = e - EE; }
    int slot = atomicAdd(&g_fill[d], 1);
    if (slot < MAXD) g_csr2[d * MAXD + slot] = s;
    if (e < NN) {
        int gi = batch[e];
        gi = (gi < 0) ? 0 : ((gi >= NG) ? NG - 1 : gi);
        atomicAdd(&g_cnt[gi], 1);
    }
}

__device__ __forceinline__ void mma_tf32(float& c0, float& c1, float& c2, float& c3,
                                         uint32_t a0, uint32_t a1, uint32_t a2, uint32_t a3,
                                         uint32_t b0, uint32_t b1) {
    asm volatile(
        "mma.sync.aligned.m16n8k8.row.col.f32.tf32.tf32.f32 "
        "{%0,%1,%2,%3},{%4,%5,%6,%7},{%8,%9},{%0,%1,%2,%3};"
        : "+f"(c0), "+f"(c1), "+f"(c2), "+f"(c3)
        : "r"(a0), "r"(a1), "r"(a2), "r"(a3), "r"(b0), "r"(b1));
}

// ---------------- tensor-core GEMM + fused alpha (tf32, raw fp32 bits) ----
// A smem k-contig (stride 36), W smem n-major (stride 36) -> conflict-free LDS.
// No cvt: tf32 MMA truncates mantissa in hardware; error ~5e-4 relative,
// attenuated ~20x by the network (measured).
#define AS_STRIDE 36
#define SM_AS 0
#define SM_WS (128 * AS_STRIDE)
#define SM_AL (2 * 128 * AS_STRIDE)
#define SMEM_FLOATS (SM_AL + 256)

__global__ __launch_bounds__(256, 2)
void gemm_tc_kernel(const float* __restrict__ A,
                    const float* __restrict__ W,
                    float* __restrict__ C, int M,
                    const float* __restrict__ a_sv,
                    const float* __restrict__ a_dv) {
    extern __shared__ float sm[];
    float* As  = sm + SM_AS;    // [row 0..127][k 0..31]  stride 36
    float* Ws  = sm + SM_WS;    // [n 0..127][k 0..31]    stride 36
    float* alS = sm + SM_AL;

    const int tid  = threadIdx.x;
    const int wid  = tid >> 5;
    const int lane = tid & 31;
    const int wm = wid & 3;
    const int wn = wid >> 2;
    const int qr = lane >> 2;
    const int qc = lane & 3;
    const int brow = blockIdx.x * 128;

    alS[tid & 255] = 0.f;

    float cfr[2][8][4];
#pragma unroll
    for (int i = 0; i < 2; i++)
#pragma unroll
        for (int j = 0; j < 8; j++)
#pragma unroll
            for (int k = 0; k < 4; k++) cfr[i][j][k] = 0.f;

    for (int kk = 0; kk < 128; kk += 32) {
        // A chunk [128 x 32] -> As[row*36 + k], float4 copies
#pragma unroll
        for (int i = 0; i < 4; i++) {
            int f4 = tid + i * 256;
            int row = f4 >> 3;
            int c4  = (f4 & 7) * 4;
            float4 v = make_float4(0.f, 0.f, 0.f, 0.f);
            if (brow + row < M)
                v = *(const float4*)&A[(brow + row) * 128 + kk + c4];
            *(float4*)&As[row * AS_STRIDE + c4] = v;
        }
        // W chunk [32 x 128] -> Ws[n*36 + k] (transpose to n-major)
#pragma unroll
        for (int i = 0; i < 4; i++) {
            int f4 = tid + i * 256;
            int row = f4 >> 5;              // k within chunk 0..31
            int c4  = (f4 & 31) * 4;        // n 0..124
            float4 v = *(const float4*)&W[(kk + row) * 128 + c4];
            Ws[(c4 + 0) * AS_STRIDE + row] = v.x;
            Ws[(c4 + 1) * AS_STRIDE + row] = v.y;
            Ws[(c4 + 2) * AS_STRIDE + row] = v.z;
            Ws[(c4 + 3) * AS_STRIDE + row] = v.w;
        }
        __syncthreads();

#pragma unroll
        for (int k8 = 0; k8 < 4; k8++) {
            const int k0 = k8 * 8 + qc;
            uint32_t ahi[2][4];
#pragma unroll
            for (int mt = 0; mt < 2; mt++) {
                int r = wm * 32 + mt * 16 + qr;
                ahi[mt][0] = __float_as_uint(As[r * AS_STRIDE + k0]);
                ahi[mt][1] = __float_as_uint(As[(r + 8) * AS_STRIDE + k0]);
                ahi[mt][2] = __float_as_uint(As[r * AS_STRIDE + k0 + 4]);
                ahi[mt][3] = __float_as_uint(As[(r + 8) * AS_STRIDE + k0 + 4]);
            }
#pragma unroll
            for (int nt = 0; nt < 8; nt++) {
                int n = wn * 64 + nt * 8 + qr;
                uint32_t bhi0 = __float_as_uint(Ws[n * AS_STRIDE + k0]);
                uint32_t bhi1 = __float_as_uint(Ws[n * AS_STRIDE + k0 + 4]);
#pragma unroll
                for (int mt = 0; mt < 2; mt++) {
                    float* c = cfr[mt][nt];
                    mma_tf32(c[0], c[1], c[2], c[3],
                             ahi[mt][0], ahi[mt][1], ahi[mt][2], ahi[mt][3],
                             bhi0, bhi1);
                }
            }
        }
        __syncthreads();
    }

#pragma unroll
    for (int mt = 0; mt < 2; mt++) {
        int r0 = wm * 32 + mt * 16 + qr;
        float ps0 = 0.f, pd0 = 0.f, ps1 = 0.f, pd1 = 0.f;
#pragma unroll
        for (int nt = 0; nt < 8; nt++) {
            int cb = wn * 64 + nt * 8 + qc * 2;
            float* c = cfr[mt][nt];
            int gr0 = brow + r0;
            if (gr0 < M)
                *(float2*)&C[gr0 * 128 + cb] = make_float2(c[0], c[1]);
            if (gr0 + 8 < M)
                *(float2*)&C[(gr0 + 8) * 128 + cb] = make_float2(c[2], c[3]);
            float s0 = a_sv[cb], s1 = a_sv[cb + 1];
            float d0 = a_dv[cb], d1 = a_dv[cb + 1];
            ps0 = fmaf(c[0], s0, fmaf(c[1], s1, ps0));
            pd0 = fmaf(c[0], d0, fmaf(c[1], d1, pd0));
            ps1 = fmaf(c[2], s0, fmaf(c[3], s1, ps1));
            pd1 = fmaf(c[2], d0, fmaf(c[3], d1, pd1));
        }
#pragma unroll
        for (int o = 1; o < 4; o <<= 1) {
            ps0 += __shfl_xor_sync(0xffffffffu, ps0, o);
            pd0 += __shfl_xor_sync(0xffffffffu, pd0, o);
            ps1 += __shfl_xor_sync(0xffffffffu, ps1, o);
            pd1 += __shfl_xor_sync(0xffffffffu, pd1, o);
        }
        if (qc == 0) {
            atomicAdd(&alS[r0], ps0);
            atomicAdd(&alS[128 + r0], pd0);
            atomicAdd(&alS[r0 + 8], ps1);
            atomicAdd(&alS[128 + r0 + 8], pd1);
        }
    }
    __syncthreads();
    if (tid < 128 && brow + tid < M) {
        g_asrc[brow + tid] = alS[tid];
        g_adst[brow + tid] = alS[128 + tid];
    }
}

// ------ warp-per-node softmax aggregation, no max pass (m = 0) ----------
template<bool POOL>
__global__ void aggregate_kernel(const float* __restrict__ h,
                                 const float* __restrict__ bias,
                                 float* __restrict__ out,
                                 const int* __restrict__ batch) {
    const unsigned FULL = 0xffffffffu;
    __shared__ float sbuf[DH];          // POOL: per-block graph partial
    const int tid  = threadIdx.x;
    const int node = (blockIdx.x * blockDim.x + tid) >> 5;
    const int lane = tid & 31;

    int gmin = 0;
    if (POOL) {
        if (tid < DH) sbuf[tid] = 0.f;
        gmin = batch[blockIdx.x * 8];   // first node of block (batch sorted)
        gmin = (gmin < 0) ? 0 : ((gmin >= NG) ? NG - 1 : gmin);
        __syncthreads();
    }

    if (node < NN) {
        const float adst_v = g_adst[node];
        const int beg = node * MAXD;
        int deg = g_fill[node];
        deg = (deg > MAXD) ? MAXD : deg;
        const int end = beg + deg;

        int   s0 = 0;
        float w0 = 0.f;
        if (beg + lane < end) {
            s0 = __ldg(&g_csr2[beg + lane]);
            float lg = __ldg(&g_asrc[s0]) + adst_v;
            lg = (lg > 0.f) ? lg : NEG_SLOPE * lg;
            w0 = __expf(lg);
        }

        float ssum = 0.f;
        float ax = 0.f, ay = 0.f, az = 0.f, aw = 0.f;

        int cnt0 = min(32, deg);
#pragma unroll 4
        for (int j = 0; j < cnt0; j++) {
            float wj = __shfl_sync(FULL, w0, j);
            int   sj = __shfl_sync(FULL, s0, j);
            float4 hv = *(const float4*)&h[sj * DH + lane * 4];
            ssum += wj;
            ax = fmaf(wj, hv.x, ax);
            ay = fmaf(wj, hv.y, ay);
            az = fmaf(wj, hv.z, az);
            aw = fmaf(wj, hv.w, aw);
        }
        for (int gb = beg + 32; gb < end; gb += 32) {
            int e = gb + lane;
            int s = 0; float w = 0.f;
            if (e < end) {
                s = __ldg(&g_csr2[e]);
                float lg = __ldg(&g_asrc[s]) + adst_v;
                lg = (lg > 0.f) ? lg : NEG_SLOPE * lg;
                w = __expf(lg);
            }
            int cnt = min(32, end - gb);
#pragma unroll 4
            for (int j = 0; j < cnt; j++) {
                float wj = __shfl_sync(FULL, w, j);
                int   sj = __shfl_sync(FULL, s, j);
                float4 hv = *(const float4*)&h[sj * DH + lane * 4];
                ssum += wj;
                ax = fmaf(wj, hv.x, ax);
                ay = fmaf(wj, hv.y, ay);
                az = fmaf(wj, hv.z, az);
                aw = fmaf(wj, hv.w, aw);
            }
        }

        float inv = 1.f / (ssum + 1e-16f);
        float4 b = *(const float4*)&bias[lane * 4];
        float ox = fmaxf(fmaf(ax, inv, b.x), 0.f);
        float oy = fmaxf(fmaf(ay, inv, b.y), 0.f);
        float oz = fmaxf(fmaf(az, inv, b.z), 0.f);
        float ow = fmaxf(fmaf(aw, inv, b.w), 0.f);

        if (POOL) {
            int gi = batch[node];
            gi = (gi < 0) ? 0 : ((gi >= NG) ? NG - 1 : gi);
            if (gi == gmin) {
                float* p = &sbuf[lane * 4];
                atomicAdd(p + 0, ox);
                atomicAdd(p + 1, oy);
                atomicAdd(p + 2, oz);
                atomicAdd(p + 3, ow);
            } else {
                float* p = &g_pooled[gi * DH + lane * 4];
                atomicAdd(p + 0, ox);
                atomicAdd(p + 1, oy);
                atomicAdd(p + 2, oz);
                atomicAdd(p + 3, ow);
            }
        } else {
            *(float4*)&out[node * DH + lane * 4] = make_float4(ox, oy, oz, ow);
        }
    }

    if (POOL) {
        __syncthreads();
        if (tid < DH) {
            float v = sbuf[tid];
            if (v != 0.f) atomicAdd(&g_pooled[gmin * DH + tid], v);
        }
    }
}

// ---------------- fused FFN head: one block per graph --------------------
__global__ __launch_bounds__(512)
void ffn_kernel(const float* __restrict__ Wf1, const float* __restrict__ bf1,
                const float* __restrict__ Wf2, const float* __restrict__ bf2,
                const float* __restrict__ Wf3, const float* __restrict__ bf3,
                float* __restrict__ out) {
    __shared__ float pz[DH];
    __shared__ float z1[DF];
    __shared__ float z2[DF];
    const int g = blockIdx.x;
    const int t = threadIdx.x;

    if (t < DH) {
        float c = (float)g_cnt[g];
        pz[t] = g_pooled[g * DH + t] / fmaxf(c, 1.f);
    }
    __syncthreads();

    {
        float acc = bf1[t];
#pragma unroll 8
        for (int k = 0; k < DH; k++)
            acc = fmaf(pz[k], Wf1[k * DF + t], acc);
        z1[t] = fmaxf(acc, 0.f);
    }
    __syncthreads();

    {
        float acc = bf2[t];
#pragma unroll 8
        for (int k = 0; k < DF; k++)
            acc = fmaf(z1[k], Wf2[k * DF + t], acc);
        z2[t] = fmaxf(acc, 0.f);
    }
    __syncthreads();

    if (t < NCLS * 16) {
        int c = t >> 4, p = t & 15;
        float acc = 0.f;
        for (int k = p * 32; k < p * 32 + 32; k++)
            acc = fmaf(z2[k], Wf3[k * NCLS + c], acc);
#pragma unroll
        for (int o = 8; o > 0; o >>= 1)
            acc += __shfl_xor_sync(0xffffffffu, acc, o);
        if (p == 0) out[g * NCLS + c] = acc + bf3[c];
    }
}

// ---------------- launch ----------------
extern "C" void kernel_launch(void* const* d_in, const int* in_sizes, int n_in,
                              void* d_out, int out_size) {
    const float* x     = (const float*)d_in[0];
    const int*   ei    = (const int*)d_in[1];
    const int*   batch = (const int*)d_in[2];
    const float* W1  = (const float*)d_in[3];
    const float* as1 = (const float*)d_in[4];
    const float* ad1 = (const float*)d_in[5];
    const float* b1  = (const float*)d_in[6];
    const float* W2  = (const float*)d_in[7];
    const float* as2 = (const float*)d_in[8];
    const float* ad2 = (const float*)d_in[9];
    const float* b2  = (const float*)d_in[10];
    const float* W3  = (const float*)d_in[11];
    const float* as3 = (const float*)d_in[12];
    const float* ad3 = (const float*)d_in[13];
    const float* b3  = (const float*)d_in[14];
    const float* Wf1 = (const float*)d_in[15];
    const float* bf1 = (const float*)d_in[16];
    const float* Wf2 = (const float*)d_in[17];
    const float* bf2 = (const float*)d_in[18];
    const float* Wf3 = (const float*)d_in[19];
    const float* bf3 = (const float*)d_in[20];
    float* out = (float*)d_out;

    float* hT;   cudaGetSymbolAddress((void**)&hT, g_hT);
    float* bufA; cudaGetSymbolAddress((void**)&bufA, g_bufA);
    float* bufB; cudaGetSymbolAddress((void**)&bufB, g_bufB);

    static int smem_set = 0;
    if (!smem_set) {
        cudaFuncSetAttribute(gemm_tc_kernel,
                             cudaFuncAttributeMaxDynamicSharedMemorySize,
                             SMEM_FLOATS * 4);
        smem_set = 1;
    }

    const int gemm_blocks = (NN + 127) / 128;
    const int warp_blocks = (NN * 32 + 255) / 256;
    const int smem_bytes = SMEM_FLOATS * 4;

    // index 0: noop (ncu skip-5 -> index 5 = gemm layer 2)
    noop_kernel<<<1, 32>>>();
    zero_kernel<<<(NN + 255) / 256, 256>>>();
    scatter_kernel<<<(ETOT + 255) / 256, 256>>>(ei, batch);

    // layer 1: x -> bufA
    gemm_tc_kernel<<<gemm_blocks, 256, smem_bytes>>>(x, W1, hT, NN, as1, ad1);
    aggregate_kernel<false><<<warp_blocks, 256>>>(hT, b1, bufA, batch);
    // layer 2: bufA -> bufB  (gemm = launch index 5 -> profiled)
    gemm_tc_kernel<<<gemm_blocks, 256, smem_bytes>>>(bufA, W2, hT, NN, as2, ad2);
    aggregate_kernel<false><<<warp_blocks, 256>>>(hT, b2, bufB, batch);
    // layer 3: bufB -> pooled (block-reduced atomics)
    gemm_tc_kernel<<<gemm_blocks, 256, smem_bytes>>>(bufB, W3, hT, NN, as3, ad3);
    aggregate_kernel<true><<<warp_blocks, 256>>>(hT, b3, bufA, batch);

    // fused head
    ffn_kernel<<<NG, 512>>>(Wf1, bf1, Wf2, bf2, Wf3, bf3, out);
}

// round 12
// speedup vs baseline: 1.0661x; 1.0661x over previous
#include <cuda_runtime.h>
#include <cstdint>

// ---------------- problem constants ----------------
#define NN 50000
#define EE 640000
#define ETOT (EE + NN)          // edges + self loops = 690000
#define DH 128                   // hidden dim
#define DF 512                   // ffn dim
#define NG 128                   // num graphs
#define NCLS 10
#define NEG_SLOPE 0.2f
#define MAXD 96                  // padded CSR row width (deg ~ Poisson(12.8)+1)

// ---------------- device scratch (no allocation allowed) ----------------
__device__ float g_hT[NN * DH];     // GEMM output
__device__ float g_bufA[NN * DH];   // layer output ping
__device__ float g_bufB[NN * DH];   // layer output pong
__device__ float g_asrc[NN];
__device__ float g_adst[NN];
__device__ int   g_fill[NN];
__device__ int   g_csr2[NN * MAXD];
__device__ float g_pooled[NG * DH];
__device__ int   g_cnt[NG];

__device__ __forceinline__ int clamp_id(int v) {
    v = (v < 0) ? 0 : v;
    return (v >= NN) ? (NN - 1) : v;
}

// ---------------- no-op (ncu launch-index steering) ----------------
__global__ void noop_kernel() {}

// ---------------- init (grid covers NN >= NG*DH) ----------------
__global__ void zero_kernel() {
    int i = blockIdx.x * blockDim.x + threadIdx.x;
    if (i < NN) g_fill[i] = 0;
    if (i < NG * DH) g_pooled[i] = 0.f;
    if (i < NG) g_cnt[i] = 0;
}

// ---------------- padded-CSR scatter (by dst) + graph counts ------------
__global__ void scatter_kernel(const int* __restrict__ ei,
                               const int* __restrict__ batch) {
    int e = blockIdx.x * blockDim.x + threadIdx.x;
    if (e >= ETOT) return;
    int s, d;
    if (e < EE) { s = clamp_id(ei[e]); d = clamp_id(ei[EE + e]); }
    else        { s = e - EE;          d = e - EE; }
    int slot = atomicAdd(&g_fill[d], 1);
    if (slot < MAXD) g_csr2[d * MAXD + slot] = s;
    if (e < NN) {
        int gi = batch[e];
        gi = (gi < 0) ? 0 : ((gi >= NG) ? NG - 1 : gi);
        atomicAdd(&g_cnt[gi], 1);
    }
}

// ---------------- tf32 helpers ----------------
__device__ __forceinline__ float tf32_rna(float x) {
    uint32_t r;
    asm("cvt.rna.tf32.f32 %0, %1;" : "=r"(r) : "f"(x));
    return __uint_as_float(r);
}

__device__ __forceinline__ void mma_tf32(float& c0, float& c1, float& c2, float& c3,
                                         uint32_t a0, uint32_t a1, uint32_t a2, uint32_t a3,
                                         uint32_t b0, uint32_t b1) {
    asm volatile(
        "mma.sync.aligned.m16n8k8.row.col.f32.tf32.tf32.f32 "
        "{%0,%1,%2,%3},{%4,%5,%6,%7},{%8,%9},{%0,%1,%2,%3};"
        : "+f"(c0), "+f"(c1), "+f"(c2), "+f"(c3)
        : "r"(a0), "r"(a1), "r"(a2), "r"(a3), "r"(b0), "r"(b1));
}

// ---------------- tensor-core GEMM + fused alpha (1-term tf32) ----------
// k-major W smem, stride 136 (mod 32 == 8) -> B fragment loads bank-free:
// bank = (k0*136 + n) mod 32 = qc*8 + qr + const, distinct for all 32 lanes.
// Stores are float4 along n (full bank coverage). A side: stride 36 ->
// bank = qr*4 + qc, distinct. Fully conflict-free smem traffic.
#define AS_STRIDE 36
#define WS_STRIDE 136
#define SM_AS 0
#define SM_WS (128 * AS_STRIDE)
#define SM_AL (128 * AS_STRIDE + 32 * WS_STRIDE)
#define SMEM_FLOATS (SM_AL + 256)

__global__ __launch_bounds__(256, 2)
void gemm_tc_kernel(const float* __restrict__ A,
                    const float* __restrict__ W,
                    float* __restrict__ C, int M,
                    const float* __restrict__ a_sv,
                    const float* __restrict__ a_dv) {
    extern __shared__ float sm[];
    float* As  = sm + SM_AS;    // [row 0..127][k 0..31]  stride 36
    float* Ws  = sm + SM_WS;    // [k 0..31][n 0..127]    stride 136
    float* alS = sm + SM_AL;

    const int tid  = threadIdx.x;
    const int wid  = tid >> 5;
    const int lane = tid & 31;
    const int wm = wid & 3;
    const int wn = wid >> 2;
    const int qr = lane >> 2;
    const int qc = lane & 3;
    const int brow = blockIdx.x * 128;

    alS[tid & 255] = 0.f;

    float cfr[2][8][4];
#pragma unroll
    for (int i = 0; i < 2; i++)
#pragma unroll
        for (int j = 0; j < 8; j++)
#pragma unroll
            for (int k = 0; k < 4; k++) cfr[i][j][k] = 0.f;

    for (int kk = 0; kk < 128; kk += 32) {
        // A chunk [128 x 32] -> As[row*36 + k]
#pragma unroll
        for (int i = 0; i < 4; i++) {
            int f4 = tid + i * 256;
            int row = f4 >> 3;
            int c4  = (f4 & 7) * 4;
            float4 v = make_float4(0.f, 0.f, 0.f, 0.f);
            if (brow + row < M)
                v = *(const float4*)&A[(brow + row) * 128 + kk + c4];
            *(float4*)&As[row * AS_STRIDE + c4] = make_float4(
                tf32_rna(v.x), tf32_rna(v.y), tf32_rna(v.z), tf32_rna(v.w));
        }
        // W chunk [32 x 128] -> Ws[k*136 + n], float4 stores along n
#pragma unroll
        for (int i = 0; i < 4; i++) {
            int f4 = tid + i * 256;
            int row = f4 >> 5;              // k 0..31
            int c4  = (f4 & 31) * 4;        // n 0..124
            float4 v = *(const float4*)&W[(kk + row) * 128 + c4];
            *(float4*)&Ws[row * WS_STRIDE + c4] = make_float4(
                tf32_rna(v.x), tf32_rna(v.y), tf32_rna(v.z), tf32_rna(v.w));
        }
        __syncthreads();

#pragma unroll
        for (int k8 = 0; k8 < 4; k8++) {
            const int k0 = k8 * 8 + qc;
            uint32_t ahi[2][4];
#pragma unroll
            for (int mt = 0; mt < 2; mt++) {
                int r = wm * 32 + mt * 16 + qr;
                ahi[mt][0] = __float_as_uint(As[r * AS_STRIDE + k0]);
                ahi[mt][1] = __float_as_uint(As[(r + 8) * AS_STRIDE + k0]);
                ahi[mt][2] = __float_as_uint(As[r * AS_STRIDE + k0 + 4]);
                ahi[mt][3] = __float_as_uint(As[(r + 8) * AS_STRIDE + k0 + 4]);
            }
#pragma unroll
            for (int nt = 0; nt < 8; nt++) {
                int n = wn * 64 + nt * 8 + qr;
                uint32_t bhi0 = __float_as_uint(Ws[k0 * WS_STRIDE + n]);
                uint32_t bhi1 = __float_as_uint(Ws[(k0 + 4) * WS_STRIDE + n]);
#pragma unroll
                for (int mt = 0; mt < 2; mt++) {
                    float* c = cfr[mt][nt];
                    mma_tf32(c[0], c[1], c[2], c[3],
                             ahi[mt][0], ahi[mt][1], ahi[mt][2], ahi[mt][3],
                             bhi0, bhi1);
                }
            }
        }
        __syncthreads();
    }

#pragma unroll
    for (int mt = 0; mt < 2; mt++) {
        int r0 = wm * 32 + mt * 16 + qr;
        float ps0 = 0.f, pd0 = 0.f, ps1 = 0.f, pd1 = 0.f;
#pragma unroll
        for (int nt = 0; nt < 8; nt++) {
            int cb = wn * 64 + nt * 8 + qc * 2;
            float* c = cfr[mt][nt];
            int gr0 = brow + r0;
            if (gr0 < M)
                *(float2*)&C[gr0 * 128 + cb] = make_float2(c[0], c[1]);
            if (gr0 + 8 < M)
                *(float2*)&C[(gr0 + 8) * 128 + cb] = make_float2(c[2], c[3]);
            float s0 = a_sv[cb], s1 = a_sv[cb + 1];
            float d0 = a_dv[cb], d1 = a_dv[cb + 1];
            ps0 = fmaf(c[0], s0, fmaf(c[1], s1, ps0));
            pd0 = fmaf(c[0], d0, fmaf(c[1], d1, pd0));
            ps1 = fmaf(c[2], s0, fmaf(c[3], s1, ps1));
            pd1 = fmaf(c[2], d0, fmaf(c[3], d1, pd1));
        }
#pragma unroll
        for (int o = 1; o < 4; o <<= 1) {
            ps0 += __shfl_xor_sync(0xffffffffu, ps0, o);
            pd0 += __shfl_xor_sync(0xffffffffu, pd0, o);
            ps1 += __shfl_xor_sync(0xffffffffu, ps1, o);
            pd1 += __shfl_xor_sync(0xffffffffu, pd1, o);
        }
        if (qc == 0) {
            atomicAdd(&alS[r0], ps0);
            atomicAdd(&alS[128 + r0], pd0);
            atomicAdd(&alS[r0 + 8], ps1);
            atomicAdd(&alS[128 + r0 + 8], pd1);
        }
    }
    __syncthreads();
    if (tid < 128 && brow + tid < M) {
        g_asrc[brow + tid] = alS[tid];
        g_adst[brow + tid] = alS[128 + tid];
    }
}

// ------ warp-per-node softmax aggregation, no max pass (m = 0) ----------
template<bool POOL>
__global__ void aggregate_kernel(const float* __restrict__ h,
                                 const float* __restrict__ bias,
                                 float* __restrict__ out,
                                 const int* __restrict__ batch) {
    const unsigned FULL = 0xffffffffu;
    __shared__ float sbuf[DH];          // POOL: per-block graph partial
    const int tid  = threadIdx.x;
    const int node = (blockIdx.x * blockDim.x + tid) >> 5;
    const int lane = tid & 31;

    int gmin = 0;
    if (POOL) {
        if (tid < DH) sbuf[tid] = 0.f;
        gmin = batch[blockIdx.x * 8];   // first node of block (batch sorted)
        gmin = (gmin < 0) ? 0 : ((gmin >= NG) ? NG - 1 : gmin);
        __syncthreads();
    }

    if (node < NN) {
        const float adst_v = g_adst[node];
        const int beg = node * MAXD;
        int deg = g_fill[node];
        deg = (deg > MAXD) ? MAXD : deg;
        const int end = beg + deg;

        int   s0 = 0;
        float w0 = 0.f;
        if (beg + lane < end) {
            s0 = __ldg(&g_csr2[beg + lane]);
            float lg = __ldg(&g_asrc[s0]) + adst_v;
            lg = (lg > 0.f) ? lg : NEG_SLOPE * lg;
            w0 = __expf(lg);
        }

        float ssum = 0.f;
        float ax = 0.f, ay = 0.f, az = 0.f, aw = 0.f;

        int cnt0 = min(32, deg);
#pragma unroll 4
        for (int j = 0; j < cnt0; j++) {
            float wj = __shfl_sync(FULL, w0, j);
            int   sj = __shfl_sync(FULL, s0, j);
            float4 hv = *(const float4*)&h[sj * DH + lane * 4];
            ssum += wj;
            ax = fmaf(wj, hv.x, ax);
            ay = fmaf(wj, hv.y, ay);
            az = fmaf(wj, hv.z, az);
            aw = fmaf(wj, hv.w, aw);
        }
        for (int gb = beg + 32; gb < end; gb += 32) {
            int e = gb + lane;
            int s = 0; float w = 0.f;
            if (e < end) {
                s = __ldg(&g_csr2[e]);
                float lg = __ldg(&g_asrc[s]) + adst_v;
                lg = (lg > 0.f) ? lg : NEG_SLOPE * lg;
                w = __expf(lg);
            }
            int cnt = min(32, end - gb);
#pragma unroll 4
            for (int j = 0; j < cnt; j++) {
                float wj = __shfl_sync(FULL, w, j);
                int   sj = __shfl_sync(FULL, s, j);
                float4 hv = *(const float4*)&h[sj * DH + lane * 4];
                ssum += wj;
                ax = fmaf(wj, hv.x, ax);
                ay = fmaf(wj, hv.y, ay);
                az = fmaf(wj, hv.z, az);
                aw = fmaf(wj, hv.w, aw);
            }
        }

        float inv = 1.f / (ssum + 1e-16f);
        float4 b = *(const float4*)&bias[lane * 4];
        float ox = fmaxf(fmaf(ax, inv, b.x), 0.f);
        float oy = fmaxf(fmaf(ay, inv, b.y), 0.f);
        float oz = fmaxf(fmaf(az, inv, b.z), 0.f);
        float ow = fmaxf(fmaf(aw, inv, b.w), 0.f);

        if (POOL) {
            int gi = batch[node];
            gi = (gi < 0) ? 0 : ((gi >= NG) ? NG - 1 : gi);
            if (gi == gmin) {
                float* p = &sbuf[lane * 4];
                atomicAdd(p + 0, ox);
                atomicAdd(p + 1, oy);
                atomicAdd(p + 2, oz);
                atomicAdd(p + 3, ow);
            } else {
                float* p = &g_pooled[gi * DH + lane * 4];
                atomicAdd(p + 0, ox);
                atomicAdd(p + 1, oy);
                atomicAdd(p + 2, oz);
                atomicAdd(p + 3, ow);
            }
        } else {
            *(float4*)&out[node * DH + lane * 4] = make_float4(ox, oy, oz, ow);
        }
    }

    if (POOL) {
        __syncthreads();
        if (tid < DH) {
            float v = sbuf[tid];
            if (v != 0.f) atomicAdd(&g_pooled[gmin * DH + tid], v);
        }
    }
}

// ---------------- fused FFN head: one block per graph --------------------
__global__ __launch_bounds__(512)
void ffn_kernel(const float* __restrict__ Wf1, const float* __restrict__ bf1,
                const float* __restrict__ Wf2, const float* __restrict__ bf2,
                const float* __restrict__ Wf3, const float* __restrict__ bf3,
                float* __restrict__ out) {
    __shared__ float pz[DH];
    __shared__ float z1[DF];
    __shared__ float z2[DF];
    const int g = blockIdx.x;
    const int t = threadIdx.x;

    if (t < DH) {
        float c = (float)g_cnt[g];
        pz[t] = g_pooled[g * DH + t] / fmaxf(c, 1.f);
    }
    __syncthreads();

    {
        float acc = bf1[t];
#pragma unroll 8
        for (int k = 0; k < DH; k++)
            acc = fmaf(pz[k], Wf1[k * DF + t], acc);
        z1[t] = fmaxf(acc, 0.f);
    }
    __syncthreads();

    {
        float acc = bf2[t];
#pragma unroll 8
        for (int k = 0; k < DF; k++)
            acc = fmaf(z1[k], Wf2[k * DF + t], acc);
        z2[t] = fmaxf(acc, 0.f);
    }
    __syncthreads();

    if (t < NCLS * 16) {
        int c = t >> 4, p = t & 15;
        float acc = 0.f;
        for (int k = p * 32; k < p * 32 + 32; k++)
            acc = fmaf(z2[k], Wf3[k * NCLS + c], acc);
#pragma unroll
        for (int o = 8; o > 0; o >>= 1)
            acc += __shfl_xor_sync(0xffffffffu, acc, o);
        if (p == 0) out[g * NCLS + c] = acc + bf3[c];
    }
}

// ---------------- launch ----------------
extern "C" void kernel_launch(void* const* d_in, const int* in_sizes, int n_in,
                              void* d_out, int out_size) {
    const float* x     = (const float*)d_in[0];
    const int*   ei    = (const int*)d_in[1];
    const int*   batch = (const int*)d_in[2];
    const float* W1  = (const float*)d_in[3];
    const float* as1 = (const float*)d_in[4];
    const float* ad1 = (const float*)d_in[5];
    const float* b1  = (const float*)d_in[6];
    const float* W2  = (const float*)d_in[7];
    const float* as2 = (const float*)d_in[8];
    const float* ad2 = (const float*)d_in[9];
    const float* b2  = (const float*)d_in[10];
    const float* W3  = (const float*)d_in[11];
    const float* as3 = (const float*)d_in[12];
    const float* ad3 = (const float*)d_in[13];
    const float* b3  = (const float*)d_in[14];
    const float* Wf1 = (const float*)d_in[15];
    const float* bf1 = (const float*)d_in[16];
    const float* Wf2 = (const float*)d_in[17];
    const float* bf2 = (const float*)d_in[18];
    const float* Wf3 = (const float*)d_in[19];
    const float* bf3 = (const float*)d_in[20];
    float* out = (float*)d_out;

    float* hT;   cudaGetSymbolAddress((void**)&hT, g_hT);
    float* bufA; cudaGetSymbolAddress((void**)&bufA, g_bufA);
    float* bufB; cudaGetSymbolAddress((void**)&bufB, g_bufB);

    static int smem_set = 0;
    if (!smem_set) {
        cudaFuncSetAttribute(gemm_tc_kernel,
                             cudaFuncAttributeMaxDynamicSharedMemorySize,
                             SMEM_FLOATS * 4);
        smem_set = 1;
    }

    const int gemm_blocks = (NN + 127) / 128;
    const int warp_blocks = (NN * 32 + 255) / 256;
    const int smem_bytes = SMEM_FLOATS * 4;

    // index 0: noop (ncu skip-5 -> index 5 = gemm layer 2)
    noop_kernel<<<1, 32>>>();
    zero_kernel<<<(NN + 255) / 256, 256>>>();
    scatter_kernel<<<(ETOT + 255) / 256, 256>>>(ei, batch);

    // layer 1: x -> bufA
    gemm_tc_kernel<<<gemm_blocks, 256, smem_bytes>>>(x, W1, hT, NN, as1, ad1);
    aggregate_kernel<false><<<warp_blocks, 256>>>(hT, b1, bufA, batch);
    // layer 2: bufA -> bufB  (gemm = launch index 5 -> profiled)
    gemm_tc_kernel<<<gemm_blocks, 256, smem_bytes>>>(bufA, W2, hT, NN, as2, ad2);
    aggregate_kernel<false><<<warp_blocks, 256>>>(hT, b2, bufB, batch);
    // layer 3: bufB -> pooled (block-reduced atomics)
    gemm_tc_kernel<<<gemm_blocks, 256, smem_bytes>>>(bufB, W3, hT, NN, as3, ad3);
    aggregate_kernel<true><<<warp_blocks, 256>>>(hT, b3, bufA, batch);

    // fused head
    ffn_kernel<<<NG, 512>>>(Wf1, bf1, Wf2, bf2, Wf3, bf3, out);
}

// round 13
// speedup vs baseline: 1.1612x; 1.0892x over previous
#include <cuda_runtime.h>
#include <cuda_bf16.h>
#include <cstdint>

// ---------------- problem constants ----------------
#define NN 50000
#define EE 640000
#define ETOT (EE + NN)          // edges + self loops = 690000
#define DH 128                   // hidden dim
#define DF 512                   // ffn dim
#define NG 128                   // num graphs
#define NCLS 10
#define NEG_SLOPE 0.2f
#define MAXD 96                  // padded CSR row width (deg ~ Poisson(12.8)+1)

// ---------------- device scratch (no allocation allowed) ----------------
__device__ float          g_hT[NN * DH];    // GEMM output (fp32, agg gathers)
__device__ __nv_bfloat16  g_xb[NN * DH];    // bf16 copy of x
__device__ __nv_bfloat16  g_bufA[NN * DH];  // layer output ping (bf16)
__device__ __nv_bfloat16  g_bufB[NN * DH];  // layer output pong (bf16)
__device__ __nv_bfloat16  g_Wb[3 * DH * DH]; // weights, n-major bf16
__device__ float g_asrc[NN];
__device__ float g_adst[NN];
__device__ int   g_fill[NN];
__device__ int   g_csr2[NN * MAXD];
__device__ float g_pooled[NG * DH];
__device__ int   g_cnt[NG];

__device__ __forceinline__ int clamp_id(int v) {
    v = (v < 0) ? 0 : v;
    return (v >= NN) ? (NN - 1) : v;
}

// ---------------- no-op (ncu launch-index steering) ----------------
__global__ void noop_kernel() {}

// ---------------- init (grid covers NN >= NG*DH) ----------------
__global__ void zero_kernel() {
    int i = blockIdx.x * blockDim.x + threadIdx.x;
    if (i < NN) g_fill[i] = 0;
    if (i < NG * DH) g_pooled[i] = 0.f;
    if (i < NG) g_cnt[i] = 0;
}

// ---------------- weight / input pre-conversion to bf16 -----------------
__global__ void cvtw_kernel(const float* __restrict__ W1,
                            const float* __restrict__ W2,
                            const float* __restrict__ W3) {
    int i = blockIdx.x * blockDim.x + threadIdx.x;
    if (i >= 3 * DH * DH) return;
    int l = i / (DH * DH);
    int r = i % (DH * DH);
    int n = r / DH, k = r % DH;
    const float* W = (l == 0) ? W1 : ((l == 1) ? W2 : W3);
    g_Wb[i] = __float2bfloat16(W[k * DH + n]);   // [l][n][k] n-major
}

__global__ void cvtx_kernel(const float* __restrict__ x) {
    int i = blockIdx.x * blockDim.x + threadIdx.x;
    if (i >= NN * DH / 4) return;
    float4 v = *(const float4*)&x[i * 4];
    __nv_bfloat162 p0, p1;
    p0.x = __float2bfloat16(v.x); p0.y = __float2bfloat16(v.y);
    p1.x = __float2bfloat16(v.z); p1.y = __float2bfloat16(v.w);
    *(__nv_bfloat162*)&g_xb[i * 4]     = p0;
    *(__nv_bfloat162*)&g_xb[i * 4 + 2] = p1;
}

// ---------------- padded-CSR scatter (by dst) + graph counts ------------
__global__ void scatter_kernel(const int* __restrict__ ei,
                               const int* __restrict__ batch) {
    int e = blockIdx.x * blockDim.x + threadIdx.x;
    if (e >= ETOT) return;
    int s, d;
    if (e < EE) { s = clamp_id(ei[e]); d = clamp_id(ei[EE + e]); }
    else        { s = e - EE;          d = e - EE; }
    int slot = atomicAdd(&g_fill[d], 1);
    if (slot < MAXD) g_csr2[d * MAXD + slot] = s;
    if (e < NN) {
        int gi = batch[e];
        gi = (gi < 0) ? 0 : ((gi >= NG) ? NG - 1 : gi);
        atomicAdd(&g_cnt[gi], 1);
    }
}

// ---------------- bf16 m16n8k16 MMA ----------------
__device__ __forceinline__ void mma_bf16(float& c0, float& c1, float& c2, float& c3,
                                         uint32_t a0, uint32_t a1, uint32_t a2, uint32_t a3,
                                         uint32_t b0, uint32_t b1) {
    asm volatile(
        "mma.sync.aligned.m16n8k16.row.col.f32.bf16.bf16.f32 "
        "{%0,%1,%2,%3},{%4,%5,%6,%7},{%8,%9},{%0,%1,%2,%3};"
        : "+f"(c0), "+f"(c1), "+f"(c2), "+f"(c3)
        : "r"(a0), "r"(a1), "r"(a2), "r"(a3), "r"(b0), "r"(b1));
}

// ---------------- bf16 tensor-core GEMM + fused alpha --------------------
// A [M][128] row-major bf16; Wn [128 n][128 k] n-major bf16; C fp32.
// smem rows stride 40 bf16 (word-stride 20 -> fragment banks qr*20+qc
// = {0,20,8,28,16,4,24,12}+qc, all 32 lanes distinct). 48 LDS + 32 MMA
// per 32-k chunk per warp (half of the tf32 version).
#define BSTR 40

__global__ __launch_bounds__(256, 2)
void gemm_bf16_kernel(const __nv_bfloat16* __restrict__ A,
                      const __nv_bfloat16* __restrict__ Wn,
                      float* __restrict__ C, int M,
                      const float* __restrict__ a_sv,
                      const float* __restrict__ a_dv) {
    __shared__ __nv_bfloat16 As[128 * BSTR];
    __shared__ __nv_bfloat16 Ws[128 * BSTR];
    __shared__ float alS[256];

    const int tid  = threadIdx.x;
    const int wid  = tid >> 5;
    const int lane = tid & 31;
    const int wm = wid & 3;
    const int wn = wid >> 2;
    const int qr = lane >> 2;
    const int qc = lane & 3;
    const int brow = blockIdx.x * 128;

    alS[tid] = 0.f;

    float cfr[2][8][4];
#pragma unroll
    for (int i = 0; i < 2; i++)
#pragma unroll
        for (int j = 0; j < 8; j++)
#pragma unroll
            for (int k = 0; k < 4; k++) cfr[i][j][k] = 0.f;

    for (int kk = 0; kk < 128; kk += 32) {
        // A chunk [128 rows x 32 k] : 512 uint4 (8 bf16) loads
#pragma unroll
        for (int i = 0; i < 2; i++) {
            int u = tid + i * 256;
            int row = u >> 2;
            int kb  = (u & 3) * 8;
            uint4 v = make_uint4(0u, 0u, 0u, 0u);
            if (brow + row < M)
                v = *(const uint4*)&A[(brow + row) * 128 + kk + kb];
            *(uint4*)&As[row * BSTR + kb] = v;
        }
        // W chunk [128 n x 32 k] (n-major source, straight copy)
#pragma unroll
        for (int i = 0; i < 2; i++) {
            int u = tid + i * 256;
            int n  = u >> 2;
            int kb = (u & 3) * 8;
            uint4 v = *(const uint4*)&Wn[n * 128 + kk + kb];
            *(uint4*)&Ws[n * BSTR + kb] = v;
        }
        __syncthreads();

#pragma unroll
        for (int k16 = 0; k16 < 2; k16++) {
            const int kb = k16 * 16 + qc * 2;
            uint32_t af[2][4];
#pragma unroll
            for (int mt = 0; mt < 2; mt++) {
                int r = wm * 32 + mt * 16 + qr;
                af[mt][0] = *(const uint32_t*)&As[r * BSTR + kb];
                af[mt][1] = *(const uint32_t*)&As[(r + 8) * BSTR + kb];
                af[mt][2] = *(const uint32_t*)&As[r * BSTR + kb + 8];
                af[mt][3] = *(const uint32_t*)&As[(r + 8) * BSTR + kb + 8];
            }
#pragma unroll
            for (int nt = 0; nt < 8; nt++) {
                int n = wn * 64 + nt * 8 + qr;
                uint32_t b0 = *(const uint32_t*)&Ws[n * BSTR + kb];
                uint32_t b1 = *(const uint32_t*)&Ws[n * BSTR + kb + 8];
#pragma unroll
                for (int mt = 0; mt < 2; mt++) {
                    float* c = cfr[mt][nt];
                    mma_bf16(c[0], c[1], c[2], c[3],
                             af[mt][0], af[mt][1], af[mt][2], af[mt][3],
                             b0, b1);
                }
            }
        }
        __syncthreads();
    }

    // epilogue: store fp32 C + fused alpha projections
#pragma unroll
    for (int mt = 0; mt < 2; mt++) {
        int r0 = wm * 32 + mt * 16 + qr;
        float ps0 = 0.f, pd0 = 0.f, ps1 = 0.f, pd1 = 0.f;
#pragma unroll
        for (int nt = 0; nt < 8; nt++) {
            int cb = wn * 64 + nt * 8 + qc * 2;
            float* c = cfr[mt][nt];
            int gr0 = brow + r0;
            if (gr0 < M)
                *(float2*)&C[gr0 * 128 + cb] = make_float2(c[0], c[1]);
            if (gr0 + 8 < M)
                *(float2*)&C[(gr0 + 8) * 128 + cb] = make_float2(c[2], c[3]);
            float s0 = a_sv[cb], s1 = a_sv[cb + 1];
            float d0 = a_dv[cb], d1 = a_dv[cb + 1];
            ps0 = fmaf(c[0], s0, fmaf(c[1], s1, ps0));
            pd0 = fmaf(c[0], d0, fmaf(c[1], d1, pd0));
            ps1 = fmaf(c[2], s0, fmaf(c[3], s1, ps1));
            pd1 = fmaf(c[2], d0, fmaf(c[3], d1, pd1));
        }
#pragma unroll
        for (int o = 1; o < 4; o <<= 1) {
            ps0 += __shfl_xor_sync(0xffffffffu, ps0, o);
            pd0 += __shfl_xor_sync(0xffffffffu, pd0, o);
            ps1 += __shfl_xor_sync(0xffffffffu, ps1, o);
            pd1 += __shfl_xor_sync(0xffffffffu, pd1, o);
        }
        if (qc == 0) {
            atomicAdd(&alS[r0], ps0);
            atomicAdd(&alS[128 + r0], pd0);
            atomicAdd(&alS[r0 + 8], ps1);
            atomicAdd(&alS[128 + r0 + 8], pd1);
        }
    }
    __syncthreads();
    if (tid < 128 && brow + tid < M) {
        g_asrc[brow + tid] = alS[tid];
        g_adst[brow + tid] = alS[128 + tid];
    }
}

// ------ warp-per-node softmax aggregation (m = 0), bf16 output ----------
template<bool POOL>
__global__ void aggregate_kernel(const float* __restrict__ h,
                                 const float* __restrict__ bias,
                                 __nv_bfloat16* __restrict__ out,
                                 const int* __restrict__ batch) {
    const unsigned FULL = 0xffffffffu;
    __shared__ float sbuf[DH];          // POOL: per-block graph partial
    const int tid  = threadIdx.x;
    const int node = (blockIdx.x * blockDim.x + tid) >> 5;
    const int lane = tid & 31;

    int gmin = 0;
    if (POOL) {
        if (tid < DH) sbuf[tid] = 0.f;
        gmin = batch[blockIdx.x * 8];   // first node of block (batch sorted)
        gmin = (gmin < 0) ? 0 : ((gmin >= NG) ? NG - 1 : gmin);
        __syncthreads();
    }

    if (node < NN) {
        const float adst_v = g_adst[node];
        const int beg = node * MAXD;
        int deg = g_fill[node];
        deg = (deg > MAXD) ? MAXD : deg;
        const int end = beg + deg;

        int   s0 = 0;
        float w0 = 0.f;
        if (beg + lane < end) {
            s0 = __ldg(&g_csr2[beg + lane]);
            float lg = __ldg(&g_asrc[s0]) + adst_v;
            lg = (lg > 0.f) ? lg : NEG_SLOPE * lg;
            w0 = __expf(lg);
        }

        float ssum = 0.f;
        float ax = 0.f, ay = 0.f, az = 0.f, aw = 0.f;

        int cnt0 = min(32, deg);
#pragma unroll 4
        for (int j = 0; j < cnt0; j++) {
            float wj = __shfl_sync(FULL, w0, j);
            int   sj = __shfl_sync(FULL, s0, j);
            float4 hv = *(const float4*)&h[sj * DH + lane * 4];
            ssum += wj;
            ax = fmaf(wj, hv.x, ax);
            ay = fmaf(wj, hv.y, ay);
            az = fmaf(wj, hv.z, az);
            aw = fmaf(wj, hv.w, aw);
        }
        for (int gb = beg + 32; gb < end; gb += 32) {
            int e = gb + lane;
            int s = 0; float w = 0.f;
            if (e < end) {
                s = __ldg(&g_csr2[e]);
                float lg = __ldg(&g_asrc[s]) + adst_v;
                lg = (lg > 0.f) ? lg : NEG_SLOPE * lg;
                w = __expf(lg);
            }
            int cnt = min(32, end - gb);
#pragma unroll 4
            for (int j = 0; j < cnt; j++) {
                float wj = __shfl_sync(FULL, w, j);
                int   sj = __shfl_sync(FULL, s, j);
                float4 hv = *(const float4*)&h[sj * DH + lane * 4];
                ssum += wj;
                ax = fmaf(wj, hv.x, ax);
                ay = fmaf(wj, hv.y, ay);
                az = fmaf(wj, hv.z, az);
                aw = fmaf(wj, hv.w, aw);
            }
        }

        float inv = 1.f / (ssum + 1e-16f);
        float4 b = *(const float4*)&bias[lane * 4];
        float ox = fmaxf(fmaf(ax, inv, b.x), 0.f);
        float oy = fmaxf(fmaf(ay, inv, b.y), 0.f);
        float oz = fmaxf(fmaf(az, inv, b.z), 0.f);
        float ow = fmaxf(fmaf(aw, inv, b.w), 0.f);

        if (POOL) {
            int gi = batch[node];
            gi = (gi < 0) ? 0 : ((gi >= NG) ? NG - 1 : gi);
            if (gi == gmin) {
                float* p = &sbuf[lane * 4];
                atomicAdd(p + 0, ox);
                atomicAdd(p + 1, oy);
                atomicAdd(p + 2, oz);
                atomicAdd(p + 3, ow);
            } else {
                float* p = &g_pooled[gi * DH + lane * 4];
                atomicAdd(p + 0, ox);
                atomicAdd(p + 1, oy);
                atomicAdd(p + 2, oz);
                atomicAdd(p + 3, ow);
            }
        } else {
            __nv_bfloat162 p0, p1;
            p0.x = __float2bfloat16(ox); p0.y = __float2bfloat16(oy);
            p1.x = __float2bfloat16(oz); p1.y = __float2bfloat16(ow);
            *(__nv_bfloat162*)&out[node * DH + lane * 4]     = p0;
            *(__nv_bfloat162*)&out[node * DH + lane * 4 + 2] = p1;
        }
    }

    if (POOL) {
        __syncthreads();
        if (tid < DH) {
            float v = sbuf[tid];
            if (v != 0.f) atomicAdd(&g_pooled[gmin * DH + tid], v);
        }
    }
}

// ---------------- fused FFN head: one block per graph --------------------
__global__ __launch_bounds__(512)
void ffn_kernel(const float* __restrict__ Wf1, const float* __restrict__ bf1,
                const float* __restrict__ Wf2, const float* __restrict__ bf2,
                const float* __restrict__ Wf3, const float* __restrict__ bf3,
                float* __restrict__ out) {
    __shared__ float pz[DH];
    __shared__ float z1[DF];
    __shared__ float z2[DF];
    const int g = blockIdx.x;
    const int t = threadIdx.x;

    if (t < DH) {
        float c = (float)g_cnt[g];
        pz[t] = g_pooled[g * DH + t] / fmaxf(c, 1.f);
    }
    __syncthreads();

    {
        float acc = bf1[t];
#pragma unroll 8
        for (int k = 0; k < DH; k++)
            acc = fmaf(pz[k], Wf1[k * DF + t], acc);
        z1[t] = fmaxf(acc, 0.f);
    }
    __syncthreads();

    {
        float acc = bf2[t];
#pragma unroll 8
        for (int k = 0; k < DF; k++)
            acc = fmaf(z1[k], Wf2[k * DF + t], acc);
        z2[t] = fmaxf(acc, 0.f);
    }
    __syncthreads();

    if (t < NCLS * 16) {
        int c = t >> 4, p = t & 15;
        float acc = 0.f;
        for (int k = p * 32; k < p * 32 + 32; k++)
            acc = fmaf(z2[k], Wf3[k * NCLS + c], acc);
#pragma unroll
        for (int o = 8; o > 0; o >>= 1)
            acc += __shfl_xor_sync(0xffffffffu, acc, o);
        if (p == 0) out[g * NCLS + c] = acc + bf3[c];
    }
}

// ---------------- launch ----------------
extern "C" void kernel_launch(void* const* d_in, const int* in_sizes, int n_in,
                              void* d_out, int out_size) {
    const float* x     = (const float*)d_in[0];
    const int*   ei    = (const int*)d_in[1];
    const int*   batch = (const int*)d_in[2];
    const float* W1  = (const float*)d_in[3];
    const float* as1 = (const float*)d_in[4];
    const float* ad1 = (const float*)d_in[5];
    const float* b1  = (const float*)d_in[6];
    const float* W2  = (const float*)d_in[7];
    const float* as2 = (const float*)d_in[8];
    const float* ad2 = (const float*)d_in[9];
    const float* b2  = (const float*)d_in[10];
    const float* W3  = (const float*)d_in[11];
    const float* as3 = (const float*)d_in[12];
    const float* ad3 = (const float*)d_in[13];
    const float* b3  = (const float*)d_in[14];
    const float* Wf1 = (const float*)d_in[15];
    const float* bf1 = (const float*)d_in[16];
    const float* Wf2 = (const float*)d_in[17];
    const float* bf2 = (const float*)d_in[18];
    const float* Wf3 = (const float*)d_in[19];
    const float* bf3 = (const float*)d_in[20];
    float* out = (float*)d_out;

    float* hT;            cudaGetSymbolAddress((void**)&hT, g_hT);
    __nv_bfloat16* xb;    cudaGetSymbolAddress((void**)&xb, g_xb);
    __nv_bfloat16* bufA;  cudaGetSymbolAddress((void**)&bufA, g_bufA);
    __nv_bfloat16* bufB;  cudaGetSymbolAddress((void**)&bufB, g_bufB);
    __nv_bfloat16* Wb;    cudaGetSymbolAddress((void**)&Wb, g_Wb);

    const int gemm_blocks = (NN + 127) / 128;
    const int warp_blocks = (NN * 32 + 255) / 256;

    // index 0..4 setup; index 5 = gemm layer 1 (profiled by ncu -s 5)
    noop_kernel<<<1, 32>>>();
    zero_kernel<<<(NN + 255) / 256, 256>>>();
    cvtw_kernel<<<(3 * DH * DH + 255) / 256, 256>>>(W1, W2, W3);
    cvtx_kernel<<<(NN * DH / 4 + 255) / 256, 256>>>(x);
    scatter_kernel<<<(ETOT + 255) / 256, 256>>>(ei, batch);

    // layer 1: xb -> bufA
    gemm_bf16_kernel<<<gemm_blocks, 256>>>(xb, Wb, hT, NN, as1, ad1);
    aggregate_kernel<false><<<warp_blocks, 256>>>(hT, b1, bufA, batch);
    // layer 2: bufA -> bufB
    gemm_bf16_kernel<<<gemm_blocks, 256>>>(bufA, Wb + DH * DH, hT, NN, as2, ad2);
    aggregate_kernel<false><<<warp_blocks, 256>>>(hT, b2, bufB, batch);
    // layer 3: bufB -> pooled (block-reduced atomics)
    gemm_bf16_kernel<<<gemm_blocks, 256>>>(bufB, Wb + 2 * DH * DH, hT, NN, as3, ad3);
    aggregate_kernel<true><<<warp_blocks, 256>>>(hT, b3, bufA, batch);

    // fused head
    ffn_kernel<<<NG, 512>>>(Wf1, bf1, Wf2, bf2, Wf3, bf3, out);
}

// round 14
// speedup vs baseline: 1.2100x; 1.0420x over previous
#include <cuda_runtime.h>
#include <cuda_bf16.h>
#include <cstdint>

// ---------------- problem constants ----------------
#define NN 50000
#define EE 640000
#define ETOT (EE + NN)          // edges + self loops = 690000
#define DH 128                   // hidden dim
#define DF 512                   // ffn dim
#define NG 128                   // num graphs
#define NCLS 10
#define NEG_SLOPE 0.2f
#define MAXD 96                  // padded CSR row width (deg ~ Poisson(12.8)+1)

// ---------------- device scratch (no allocation allowed) ----------------
__device__ float          g_hT[NN * DH];    // GEMM output (fp32, agg gathers)
__device__ __nv_bfloat16  g_bufA[NN * DH];  // layer output ping (bf16)
__device__ __nv_bfloat16  g_bufB[NN * DH];  // layer output pong (bf16)
__device__ __nv_bfloat16  g_Wb[3 * DH * DH]; // weights, n-major bf16
__device__ float g_asrc[NN];
__device__ float g_adst[NN];
__device__ int   g_fill[NN];
__device__ int   g_csr2[NN * MAXD];
__device__ float g_pooled[NG * DH];
__device__ int   g_cnt[NG];

__device__ __forceinline__ int clamp_id(int v) {
    v = (v < 0) ? 0 : v;
    return (v >= NN) ? (NN - 1) : v;
}

// ---------------- init (grid covers NN >= NG*DH) ----------------
__global__ void zero_kernel() {
    int i = blockIdx.x * blockDim.x + threadIdx.x;
    if (i < NN) g_fill[i] = 0;
    if (i < NG * DH) g_pooled[i] = 0.f;
    if (i < NG) g_cnt[i] = 0;
}

// ---------------- weight pre-conversion to n-major bf16 -----------------
__global__ void cvtw_kernel(const float* __restrict__ W1,
                            const float* __restrict__ W2,
                            const float* __restrict__ W3) {
    int i = blockIdx.x * blockDim.x + threadIdx.x;
    if (i >= 3 * DH * DH) return;
    int l = i / (DH * DH);
    int r = i % (DH * DH);
    int n = r / DH, k = r % DH;
    const float* W = (l == 0) ? W1 : ((l == 1) ? W2 : W3);
    g_Wb[i] = __float2bfloat16(W[k * DH + n]);   // [l][n][k] n-major
}

// ---------------- padded-CSR scatter (by dst) + graph counts ------------
__global__ void scatter_kernel(const int* __restrict__ ei,
                               const int* __restrict__ batch) {
    int e = blockIdx.x * blockDim.x + threadIdx.x;
    if (e >= ETOT) return;
    int s, d;
    if (e < EE) { s = clamp_id(ei[e]); d = clamp_id(ei[EE + e]); }
    else        { s = e - EE;          d = e - EE; }
    int slot = atomicAdd(&g_fill[d], 1);
    if (slot < MAXD) g_csr2[d * MAXD + slot] = s;
    if (e < NN) {
        int gi = batch[e];
        gi = (gi < 0) ? 0 : ((gi >= NG) ? NG - 1 : gi);
        atomicAdd(&g_cnt[gi], 1);
    }
}

// ---------------- bf16 m16n8k16 MMA ----------------
__device__ __forceinline__ void mma_bf16(float& c0, float& c1, float& c2, float& c3,
                                         uint32_t a0, uint32_t a1, uint32_t a2, uint32_t a3,
                                         uint32_t b0, uint32_t b1) {
    asm volatile(
        "mma.sync.aligned.m16n8k16.row.col.f32.bf16.bf16.f32 "
        "{%0,%1,%2,%3},{%4,%5,%6,%7},{%8,%9},{%0,%1,%2,%3};"
        : "+f"(c0), "+f"(c1), "+f"(c2), "+f"(c3)
        : "r"(a0), "r"(a1), "r"(a2), "r"(a3), "r"(b0), "r"(b1));
}

__device__ __forceinline__ uint32_t pack_bf2(float a, float b) {
    __nv_bfloat162 t = __floats2bfloat162_rn(a, b);
    return *reinterpret_cast<uint32_t*>(&t);
}

// ---------------- bf16 tensor-core GEMM + fused alpha --------------------
// A: bf16 row-major OR fp32 row-major (converted in the load phase).
// Wn [128 n][128 k] n-major bf16; C fp32. smem stride 40 bf16 -> all
// fragment loads bank-conflict-free. 48 LDS + 32 MMA per 32-k chunk.
#define BSTR 40

template<typename T>
__global__ __launch_bounds__(256, 2)
void gemm_bf16_kernel(const T* __restrict__ A,
                      const __nv_bfloat16* __restrict__ Wn,
                      float* __restrict__ C, int M,
                      const float* __restrict__ a_sv,
                      const float* __restrict__ a_dv) {
    constexpr bool F32IN = (sizeof(T) == 4);
    __shared__ __nv_bfloat16 As[128 * BSTR];
    __shared__ __nv_bfloat16 Ws[128 * BSTR];
    __shared__ float alS[256];

    const int tid  = threadIdx.x;
    const int wid  = tid >> 5;
    const int lane = tid & 31;
    const int wm = wid & 3;
    const int wn = wid >> 2;
    const int qr = lane >> 2;
    const int qc = lane & 3;
    const int brow = blockIdx.x * 128;

    alS[tid] = 0.f;

    float cfr[2][8][4];
#pragma unroll
    for (int i = 0; i < 2; i++)
#pragma unroll
        for (int j = 0; j < 8; j++)
#pragma unroll
            for (int k = 0; k < 4; k++) cfr[i][j][k] = 0.f;

    for (int kk = 0; kk < 128; kk += 32) {
        // A chunk [128 rows x 32 k]
#pragma unroll
        for (int i = 0; i < 2; i++) {
            int u = tid + i * 256;
            int row = u >> 2;
            int kb  = (u & 3) * 8;
            uint4 v = make_uint4(0u, 0u, 0u, 0u);
            if (brow + row < M) {
                if (F32IN) {
                    const float* Af = (const float*)A;
                    float4 v0 = *(const float4*)&Af[(brow + row) * 128 + kk + kb];
                    float4 v1 = *(const float4*)&Af[(brow + row) * 128 + kk + kb + 4];
                    v.x = pack_bf2(v0.x, v0.y);
                    v.y = pack_bf2(v0.z, v0.w);
                    v.z = pack_bf2(v1.x, v1.y);
                    v.w = pack_bf2(v1.z, v1.w);
                } else {
                    v = *(const uint4*)&((const __nv_bfloat16*)A)[(brow + row) * 128 + kk + kb];
                }
            }
            *(uint4*)&As[row * BSTR + kb] = v;
        }
        // W chunk [128 n x 32 k] (n-major source, straight copy)
#pragma unroll
        for (int i = 0; i < 2; i++) {
            int u = tid + i * 256;
            int n  = u >> 2;
            int kb = (u & 3) * 8;
            uint4 v = *(const uint4*)&Wn[n * 128 + kk + kb];
            *(uint4*)&Ws[n * BSTR + kb] = v;
        }
        __syncthreads();

#pragma unroll
        for (int k16 = 0; k16 < 2; k16++) {
            const int kb = k16 * 16 + qc * 2;
            uint32_t af[2][4];
#pragma unroll
            for (int mt = 0; mt < 2; mt++) {
                int r = wm * 32 + mt * 16 + qr;
                af[mt][0] = *(const uint32_t*)&As[r * BSTR + kb];
                af[mt][1] = *(const uint32_t*)&As[(r + 8) * BSTR + kb];
                af[mt][2] = *(const uint32_t*)&As[r * BSTR + kb + 8];
                af[mt][3] = *(const uint32_t*)&As[(r + 8) * BSTR + kb + 8];
            }
#pragma unroll
            for (int nt = 0; nt < 8; nt++) {
                int n = wn * 64 + nt * 8 + qr;
                uint32_t b0 = *(const uint32_t*)&Ws[n * BSTR + kb];
                uint32_t b1 = *(const uint32_t*)&Ws[n * BSTR + kb + 8];
#pragma unroll
                for (int mt = 0; mt < 2; mt++) {
                    float* c = cfr[mt][nt];
                    mma_bf16(c[0], c[1], c[2], c[3],
                             af[mt][0], af[mt][1], af[mt][2], af[mt][3],
                             b0, b1);
                }
            }
        }
        __syncthreads();
    }

    // epilogue: store fp32 C + fused alpha projections
#pragma unroll
    for (int mt = 0; mt < 2; mt++) {
        int r0 = wm * 32 + mt * 16 + qr;
        float ps0 = 0.f, pd0 = 0.f, ps1 = 0.f, pd1 = 0.f;
#pragma unroll
        for (int nt = 0; nt < 8; nt++) {
            int cb = wn * 64 + nt * 8 + qc * 2;
            float* c = cfr[mt][nt];
            int gr0 = brow + r0;
            if (gr0 < M)
                *(float2*)&C[gr0 * 128 + cb] = make_float2(c[0], c[1]);
            if (gr0 + 8 < M)
                *(float2*)&C[(gr0 + 8) * 128 + cb] = make_float2(c[2], c[3]);
            float s0 = a_sv[cb], s1 = a_sv[cb + 1];
            float d0 = a_dv[cb], d1 = a_dv[cb + 1];
            ps0 = fmaf(c[0], s0, fmaf(c[1], s1, ps0));
            pd0 = fmaf(c[0], d0, fmaf(c[1], d1, pd0));
            ps1 = fmaf(c[2], s0, fmaf(c[3], s1, ps1));
            pd1 = fmaf(c[2], d0, fmaf(c[3], d1, pd1));
        }
#pragma unroll
        for (int o = 1; o < 4; o <<= 1) {
            ps0 += __shfl_xor_sync(0xffffffffu, ps0, o);
            pd0 += __shfl_xor_sync(0xffffffffu, pd0, o);
            ps1 += __shfl_xor_sync(0xffffffffu, ps1, o);
            pd1 += __shfl_xor_sync(0xffffffffu, pd1, o);
        }
        if (qc == 0) {
            atomicAdd(&alS[r0], ps0);
            atomicAdd(&alS[128 + r0], pd0);
            atomicAdd(&alS[r0 + 8], ps1);
            atomicAdd(&alS[128 + r0 + 8], pd1);
        }
    }
    __syncthreads();
    if (tid < 128 && brow + tid < M) {
        g_asrc[brow + tid] = alS[tid];
        g_adst[brow + tid] = alS[128 + tid];
    }
}

// ------ warp-per-node softmax aggregation (m = 0), bf16 output ----------
template<bool POOL>
__global__ void aggregate_kernel(const float* __restrict__ h,
                                 const float* __restrict__ bias,
                                 __nv_bfloat16* __restrict__ out,
                                 const int* __restrict__ batch) {
    const unsigned FULL = 0xffffffffu;
    __shared__ float sbuf[DH];          // POOL: per-block graph partial
    const int tid  = threadIdx.x;
    const int node = (blockIdx.x * blockDim.x + tid) >> 5;
    const int lane = tid & 31;

    int gmin = 0;
    if (POOL) {
        if (tid < DH) sbuf[tid] = 0.f;
        gmin = batch[blockIdx.x * 8];   // first node of block (batch sorted)
        gmin = (gmin < 0) ? 0 : ((gmin >= NG) ? NG - 1 : gmin);
        __syncthreads();
    }

    if (node < NN) {
        const float adst_v = g_adst[node];
        const int beg = node * MAXD;
        int deg = g_fill[node];
        deg = (deg > MAXD) ? MAXD : deg;
        const int end = beg + deg;

        int   s0 = 0;
        float w0 = 0.f;
        if (beg + lane < end) {
            s0 = __ldg(&g_csr2[beg + lane]);
            float lg = __ldg(&g_asrc[s0]) + adst_v;
            lg = (lg > 0.f) ? lg : NEG_SLOPE * lg;
            w0 = __expf(lg);
        }

        float ssum = 0.f;
        float ax = 0.f, ay = 0.f, az = 0.f, aw = 0.f;

        int cnt0 = min(32, deg);
#pragma unroll 4
        for (int j = 0; j < cnt0; j++) {
            float wj = __shfl_sync(FULL, w0, j);
            int   sj = __shfl_sync(FULL, s0, j);
            float4 hv = *(const float4*)&h[sj * DH + lane * 4];
            ssum += wj;
            ax = fmaf(wj, hv.x, ax);
            ay = fmaf(wj, hv.y, ay);
            az = fmaf(wj, hv.z, az);
            aw = fmaf(wj, hv.w, aw);
        }
        for (int gb = beg + 32; gb < end; gb += 32) {
            int e = gb + lane;
            int s = 0; float w = 0.f;
            if (e < end) {
                s = __ldg(&g_csr2[e]);
                float lg = __ldg(&g_asrc[s]) + adst_v;
                lg = (lg > 0.f) ? lg : NEG_SLOPE * lg;
                w = __expf(lg);
            }
            int cnt = min(32, end - gb);
#pragma unroll 4
            for (int j = 0; j < cnt; j++) {
                float wj = __shfl_sync(FULL, w, j);
                int   sj = __shfl_sync(FULL, s, j);
                float4 hv = *(const float4*)&h[sj * DH + lane * 4];
                ssum += wj;
                ax = fmaf(wj, hv.x, ax);
                ay = fmaf(wj, hv.y, ay);
                az = fmaf(wj, hv.z, az);
                aw = fmaf(wj, hv.w, aw);
            }
        }

        float inv = 1.f / (ssum + 1e-16f);
        float4 b = *(const float4*)&bias[lane * 4];
        float ox = fmaxf(fmaf(ax, inv, b.x), 0.f);
        float oy = fmaxf(fmaf(ay, inv, b.y), 0.f);
        float oz = fmaxf(fmaf(az, inv, b.z), 0.f);
        float ow = fmaxf(fmaf(aw, inv, b.w), 0.f);

        if (POOL) {
            int gi = batch[node];
            gi = (gi < 0) ? 0 : ((gi >= NG) ? NG - 1 : gi);
            if (gi == gmin) {
                float* p = &sbuf[lane * 4];
                atomicAdd(p + 0, ox);
                atomicAdd(p + 1, oy);
                atomicAdd(p + 2, oz);
                atomicAdd(p + 3, ow);
            } else {
                float* p = &g_pooled[gi * DH + lane * 4];
                atomicAdd(p + 0, ox);
                atomicAdd(p + 1, oy);
                atomicAdd(p + 2, oz);
                atomicAdd(p + 3, ow);
            }
        } else {
            __nv_bfloat162 p0, p1;
            p0.x = __float2bfloat16(ox); p0.y = __float2bfloat16(oy);
            p1.x = __float2bfloat16(oz); p1.y = __float2bfloat16(ow);
            *(__nv_bfloat162*)&out[node * DH + lane * 4]     = p0;
            *(__nv_bfloat162*)&out[node * DH + lane * 4 + 2] = p1;
        }
    }

    if (POOL) {
        __syncthreads();
        if (tid < DH) {
            float v = sbuf[tid];
            if (v != 0.f) atomicAdd(&g_pooled[gmin * DH + tid], v);
        }
    }
}

// ---------------- fused FFN head: one block per graph --------------------
__global__ __launch_bounds__(512)
void ffn_kernel(const float* __restrict__ Wf1, const float* __restrict__ bf1,
                const float* __restrict__ Wf2, const float* __restrict__ bf2,
                const float* __restrict__ Wf3, const float* __restrict__ bf3,
                float* __restrict__ out) {
    __shared__ float pz[DH];
    __shared__ float z1[DF];
    __shared__ float z2[DF];
    const int g = blockIdx.x;
    const int t = threadIdx.x;

    if (t < DH) {
        float c = (float)g_cnt[g];
        pz[t] = g_pooled[g * DH + t] / fmaxf(c, 1.f);
    }
    __syncthreads();

    {
        float acc = bf1[t];
#pragma unroll 8
        for (int k = 0; k < DH; k++)
            acc = fmaf(pz[k], Wf1[k * DF + t], acc);
        z1[t] = fmaxf(acc, 0.f);
    }
    __syncthreads();

    {
        float acc = bf2[t];
#pragma unroll 8
        for (int k = 0; k < DF; k++)
            acc = fmaf(z1[k], Wf2[k * DF + t], acc);
        z2[t] = fmaxf(acc, 0.f);
    }
    __syncthreads();

    if (t < NCLS * 16) {
        int c = t >> 4, p = t & 15;
        float acc = 0.f;
        for (int k = p * 32; k < p * 32 + 32; k++)
            acc = fmaf(z2[k], Wf3[k * NCLS + c], acc);
#pragma unroll
        for (int o = 8; o > 0; o >>= 1)
            acc += __shfl_xor_sync(0xffffffffu, acc, o);
        if (p == 0) out[g * NCLS + c] = acc + bf3[c];
    }
}

// ---------------- launch ----------------
extern "C" void kernel_launch(void* const* d_in, const int* in_sizes, int n_in,
                              void* d_out, int out_size) {
    const float* x     = (const float*)d_in[0];
    const int*   ei    = (const int*)d_in[1];
    const int*   batch = (const int*)d_in[2];
    const float* W1  = (const float*)d_in[3];
    const float* as1 = (const float*)d_in[4];
    const float* ad1 = (const float*)d_in[5];
    const float* b1  = (const float*)d_in[6];
    const float* W2  = (const float*)d_in[7];
    const float* as2 = (const float*)d_in[8];
    const float* ad2 = (const float*)d_in[9];
    const float* b2  = (const float*)d_in[10];
    const float* W3  = (const float*)d_in[11];
    const float* as3 = (const float*)d_in[12];
    const float* ad3 = (const float*)d_in[13];
    const float* b3  = (const float*)d_in[14];
    const float* Wf1 = (const float*)d_in[15];
    const float* bf1 = (const float*)d_in[16];
    const float* Wf2 = (const float*)d_in[17];
    const float* bf2 = (const float*)d_in[18];
    const float* Wf3 = (const float*)d_in[19];
    const float* bf3 = (const float*)d_in[20];
    float* out = (float*)d_out;

    float* hT;            cudaGetSymbolAddress((void**)&hT, g_hT);
    __nv_bfloat16* bufA;  cudaGetSymbolAddress((void**)&bufA, g_bufA);
    __nv_bfloat16* bufB;  cudaGetSymbolAddress((void**)&bufB, g_bufB);
    __nv_bfloat16* Wb;    cudaGetSymbolAddress((void**)&Wb, g_Wb);

    // side stream + events, created on the first (uncaptured) call
    static cudaStream_t s2 = nullptr;
    static cudaEvent_t evFork = nullptr, evJoin = nullptr;
    if (!s2) {
        cudaStreamCreateWithFlags(&s2, cudaStreamNonBlocking);
        cudaEventCreateWithFlags(&evFork, cudaEventDisableTiming);
        cudaEventCreateWithFlags(&evJoin, cudaEventDisableTiming);
    }

    const int gemm_blocks = (NN + 127) / 128;
    const int warp_blocks = (NN * 32 + 255) / 256;

    // fork: CSR build on s2, concurrent with cvtw + gemm layer 1
    cudaEventRecord(evFork, 0);
    cudaStreamWaitEvent(s2, evFork, 0);
    zero_kernel<<<(NN + 255) / 256, 256, 0, s2>>>();
    scatter_kernel<<<(ETOT + 255) / 256, 256, 0, s2>>>(ei, batch);
    cudaEventRecord(evJoin, s2);

    cvtw_kernel<<<(3 * DH * DH + 255) / 256, 256>>>(W1, W2, W3);
    // layer 1 GEMM consumes fp32 x directly (fused conversion)
    gemm_bf16_kernel<float><<<gemm_blocks, 256>>>(x, Wb, hT, NN, as1, ad1);

    // join: aggregation needs the CSR
    cudaStreamWaitEvent(0, evJoin, 0);
    aggregate_kernel<false><<<warp_blocks, 256>>>(hT, b1, bufA, batch);
    // layer 2 (gemm here = launch index 5 -> profiled)
    gemm_bf16_kernel<__nv_bfloat16><<<gemm_blocks, 256>>>(bufA, Wb + DH * DH, hT, NN, as2, ad2);
    aggregate_kernel<false><<<warp_blocks, 256>>>(hT, b2, bufB, batch);
    // layer 3 -> pooled
    gemm_bf16_kernel<__nv_bfloat16><<<gemm_blocks, 256>>>(bufB, Wb + 2 * DH * DH, hT, NN, as3, ad3);
    aggregate_kernel<true><<<warp_blocks, 256>>>(hT, b3, bufA, batch);

    // fused head
    ffn_kernel<<<NG, 512>>>(Wf1, bf1, Wf2, bf2, Wf3, bf3, out);
}

// round 15
// speedup vs baseline: 1.2572x; 1.0390x over previous
#include <cuda_runtime.h>
#include <cuda_bf16.h>
#include <cstdint>

// ---------------- problem constants ----------------
#define NN 50000
#define EE 640000
#define ETOT (EE + NN)          // edges + self loops = 690000
#define DH 128                   // hidden dim
#define DF 512                   // ffn dim
#define NG 128                   // num graphs
#define NCLS 10
#define NEG_SLOPE 0.2f
#define MAXD 96                  // padded CSR row width (deg ~ Poisson(12.8)+1)

// ---------------- device scratch (no allocation allowed) ----------------
__device__ float          g_hT[NN * DH];    // GEMM output (fp32, agg gathers)
__device__ __nv_bfloat16  g_bufA[NN * DH];  // layer output ping (bf16)
__device__ __nv_bfloat16  g_bufB[NN * DH];  // layer output pong (bf16)
__device__ __nv_bfloat16  g_Wb[3 * DH * DH]; // weights, n-major bf16
__device__ float g_asrc[NN];
__device__ float g_adst[NN];
__device__ int   g_fill[NN];
__device__ int   g_csr2[NN * MAXD];
__device__ float g_pooled[NG * DH];
__device__ int   g_cnt[NG];

__device__ __forceinline__ int clamp_id(int v) {
    v = (v < 0) ? 0 : v;
    return (v >= NN) ? (NN - 1) : v;
}

// ---------------- init (grid covers NN >= NG*DH) ----------------
__global__ void zero_kernel() {
    int i = blockIdx.x * blockDim.x + threadIdx.x;
    if (i < NN) g_fill[i] = 0;
    if (i < NG * DH) g_pooled[i] = 0.f;
    if (i < NG) g_cnt[i] = 0;
}

// ---------------- weight pre-conversion to n-major bf16 -----------------
__global__ void cvtw_kernel(const float* __restrict__ W1,
                            const float* __restrict__ W2,
                            const float* __restrict__ W3) {
    int i = blockIdx.x * blockDim.x + threadIdx.x;
    if (i >= 3 * DH * DH) return;
    int l = i / (DH * DH);
    int r = i % (DH * DH);
    int n = r / DH, k = r % DH;
    const float* W = (l == 0) ? W1 : ((l == 1) ? W2 : W3);
    g_Wb[i] = __float2bfloat16(W[k * DH + n]);   // [l][n][k] n-major
}

// ---------------- padded-CSR scatter (by dst) + graph counts ------------
__global__ void scatter_kernel(const int* __restrict__ ei,
                               const int* __restrict__ batch) {
    int e = blockIdx.x * blockDim.x + threadIdx.x;
    if (e >= ETOT) return;
    int s, d;
    if (e < EE) { s = clamp_id(ei[e]); d = clamp_id(ei[EE + e]); }
    else        { s = e - EE;          d = e - EE; }
    int slot = atomicAdd(&g_fill[d], 1);
    if (slot < MAXD) g_csr2[d * MAXD + slot] = s;
    if (e < NN) {
        int gi = batch[e];
        gi = (gi < 0) ? 0 : ((gi >= NG) ? NG - 1 : gi);
        atomicAdd(&g_cnt[gi], 1);
    }
}

// ---------------- bf16 m16n8k16 MMA ----------------
__device__ __forceinline__ void mma_bf16(float& c0, float& c1, float& c2, float& c3,
                                         uint32_t a0, uint32_t a1, uint32_t a2, uint32_t a3,
                                         uint32_t b0, uint32_t b1) {
    asm volatile(
        "mma.sync.aligned.m16n8k16.row.col.f32.bf16.bf16.f32 "
        "{%0,%1,%2,%3},{%4,%5,%6,%7},{%8,%9},{%0,%1,%2,%3};"
        : "+f"(c0), "+f"(c1), "+f"(c2), "+f"(c3)
        : "r"(a0), "r"(a1), "r"(a2), "r"(a3), "r"(b0), "r"(b1));
}

__device__ __forceinline__ uint32_t pack_bf2(float a, float b) {
    __nv_bfloat162 t = __floats2bfloat162_rn(a, b);
    return *reinterpret_cast<uint32_t*>(&t);
}

// ---------------- single-phase bf16 GEMM + fused alpha -------------------
// Whole K=128 tiles staged in smem (stride 136 bf16 -> word-stride 68 == 4
// mod 32 -> fragment banks qr*4+qc, conflict-free). ONE load phase with 8
// independent uint4 LDGs per thread (high MLP), ONE sync, then 8 k16 MMA
// steps with no further barriers.
#define BSTR 136
#define SMEM_BYTES (2 * 128 * BSTR * 2 + 256 * 4)   // As + Ws + alS = 70656

template<typename T>
__global__ __launch_bounds__(256, 2)
void gemm_bf16_kernel(const T* __restrict__ A,
                      const __nv_bfloat16* __restrict__ Wn,
                      float* __restrict__ C, int M,
                      const float* __restrict__ a_sv,
                      const float* __restrict__ a_dv) {
    constexpr bool F32IN = (sizeof(T) == 4);
    extern __shared__ char smem_raw[];
    __nv_bfloat16* As = (__nv_bfloat16*)smem_raw;          // [128][BSTR]
    __nv_bfloat16* Ws = As + 128 * BSTR;                   // [128][BSTR]
    float*        alS = (float*)(Ws + 128 * BSTR);         // [256]

    const int tid  = threadIdx.x;
    const int wid  = tid >> 5;
    const int lane = tid & 31;
    const int wm = wid & 3;
    const int wn = wid >> 2;
    const int qr = lane >> 2;
    const int qc = lane & 3;
    const int brow = blockIdx.x * 128;

    alS[tid] = 0.f;

    // ---- load full A tile [128 x 128] ----
#pragma unroll
    for (int i = 0; i < 8; i++) {
        int u = tid + i * 256;
        int row = u >> 4;           // 16 uint4 per row
        int kb  = (u & 15) * 8;
        uint4 v = make_uint4(0u, 0u, 0u, 0u);
        if (brow + row < M) {
            if (F32IN) {
                const float* Af = (const float*)A;
                float4 v0 = *(const float4*)&Af[(brow + row) * 128 + kb];
                float4 v1 = *(const float4*)&Af[(brow + row) * 128 + kb + 4];
                v.x = pack_bf2(v0.x, v0.y);
                v.y = pack_bf2(v0.z, v0.w);
                v.z = pack_bf2(v1.x, v1.y);
                v.w = pack_bf2(v1.z, v1.w);
            } else {
                v = *(const uint4*)&((const __nv_bfloat16*)A)[(brow + row) * 128 + kb];
            }
        }
        *(uint4*)&As[row * BSTR + kb] = v;
    }
    // ---- load full W tile [128 n x 128 k] (n-major source) ----
#pragma unroll
    for (int i = 0; i < 8; i++) {
        int u = tid + i * 256;
        int n  = u >> 4;
        int kb = (u & 15) * 8;
        uint4 v = *(const uint4*)&Wn[n * 128 + kb];
        *(uint4*)&Ws[n * BSTR + kb] = v;
    }
    __syncthreads();

    float cfr[2][8][4];
#pragma unroll
    for (int i = 0; i < 2; i++)
#pragma unroll
        for (int j = 0; j < 8; j++)
#pragma unroll
            for (int k = 0; k < 4; k++) cfr[i][j][k] = 0.f;

#pragma unroll
    for (int k16 = 0; k16 < 8; k16++) {
        const int kb = k16 * 16 + qc * 2;
        uint32_t af[2][4];
#pragma unroll
        for (int mt = 0; mt < 2; mt++) {
            int r = wm * 32 + mt * 16 + qr;
            af[mt][0] = *(const uint32_t*)&As[r * BSTR + kb];
            af[mt][1] = *(const uint32_t*)&As[(r + 8) * BSTR + kb];
            af[mt][2] = *(const uint32_t*)&As[r * BSTR + kb + 8];
            af[mt][3] = *(const uint32_t*)&As[(r + 8) * BSTR + kb + 8];
        }
#pragma unroll
        for (int nt = 0; nt < 8; nt++) {
            int n = wn * 64 + nt * 8 + qr;
            uint32_t b0 = *(const uint32_t*)&Ws[n * BSTR + kb];
            uint32_t b1 = *(const uint32_t*)&Ws[n * BSTR + kb + 8];
#pragma unroll
            for (int mt = 0; mt < 2; mt++) {
                float* c = cfr[mt][nt];
                mma_bf16(c[0], c[1], c[2], c[3],
                         af[mt][0], af[mt][1], af[mt][2], af[mt][3],
                         b0, b1);
            }
        }
    }

    // epilogue: store fp32 C + fused alpha projections
#pragma unroll
    for (int mt = 0; mt < 2; mt++) {
        int r0 = wm * 32 + mt * 16 + qr;
        float ps0 = 0.f, pd0 = 0.f, ps1 = 0.f, pd1 = 0.f;
#pragma unroll
        for (int nt = 0; nt < 8; nt++) {
            int cb = wn * 64 + nt * 8 + qc * 2;
            float* c = cfr[mt][nt];
            int gr0 = brow + r0;
            if (gr0 < M)
                *(float2*)&C[gr0 * 128 + cb] = make_float2(c[0], c[1]);
            if (gr0 + 8 < M)
                *(float2*)&C[(gr0 + 8) * 128 + cb] = make_float2(c[2], c[3]);
            float s0 = a_sv[cb], s1 = a_sv[cb + 1];
            float d0 = a_dv[cb], d1 = a_dv[cb + 1];
            ps0 = fmaf(c[0], s0, fmaf(c[1], s1, ps0));
            pd0 = fmaf(c[0], d0, fmaf(c[1], d1, pd0));
            ps1 = fmaf(c[2], s0, fmaf(c[3], s1, ps1));
            pd1 = fmaf(c[2], d0, fmaf(c[3], d1, pd1));
        }
#pragma unroll
        for (int o = 1; o < 4; o <<= 1) {
            ps0 += __shfl_xor_sync(0xffffffffu, ps0, o);
            pd0 += __shfl_xor_sync(0xffffffffu, pd0, o);
            ps1 += __shfl_xor_sync(0xffffffffu, ps1, o);
            pd1 += __shfl_xor_sync(0xffffffffu, pd1, o);
        }
        if (qc == 0) {
            atomicAdd(&alS[r0], ps0);
            atomicAdd(&alS[128 + r0], pd0);
            atomicAdd(&alS[r0 + 8], ps1);
            atomicAdd(&alS[128 + r0 + 8], pd1);
        }
    }
    __syncthreads();
    if (tid < 128 && brow + tid < M) {
        g_asrc[brow + tid] = alS[tid];
        g_adst[brow + tid] = alS[128 + tid];
    }
}

// ------ warp-per-node softmax aggregation (m = 0), bf16 output ----------
template<bool POOL>
__global__ void aggregate_kernel(const float* __restrict__ h,
                                 const float* __restrict__ bias,
                                 __nv_bfloat16* __restrict__ out,
                                 const int* __restrict__ batch) {
    const unsigned FULL = 0xffffffffu;
    __shared__ float sbuf[DH];          // POOL: per-block graph partial
    const int tid  = threadIdx.x;
    const int node = (blockIdx.x * blockDim.x + tid) >> 5;
    const int lane = tid & 31;

    int gmin = 0;
    if (POOL) {
        if (tid < DH) sbuf[tid] = 0.f;
        gmin = batch[blockIdx.x * 8];   // first node of block (batch sorted)
        gmin = (gmin < 0) ? 0 : ((gmin >= NG) ? NG - 1 : gmin);
        __syncthreads();
    }

    if (node < NN) {
        const float adst_v = g_adst[node];
        const int beg = node * MAXD;
        int deg = g_fill[node];
        deg = (deg > MAXD) ? MAXD : deg;
        const int end = beg + deg;

        int   s0 = 0;
        float w0 = 0.f;
        if (beg + lane < end) {
            s0 = __ldg(&g_csr2[beg + lane]);
            float lg = __ldg(&g_asrc[s0]) + adst_v;
            lg = (lg > 0.f) ? lg : NEG_SLOPE * lg;
            w0 = __expf(lg);
        }

        float ssum = 0.f;
        float ax = 0.f, ay = 0.f, az = 0.f, aw = 0.f;

        int cnt0 = min(32, deg);
#pragma unroll 4
        for (int j = 0; j < cnt0; j++) {
            float wj = __shfl_sync(FULL, w0, j);
            int   sj = __shfl_sync(FULL, s0, j);
            float4 hv = *(const float4*)&h[sj * DH + lane * 4];
            ssum += wj;
            ax = fmaf(wj, hv.x, ax);
            ay = fmaf(wj, hv.y, ay);
            az = fmaf(wj, hv.z, az);
            aw = fmaf(wj, hv.w, aw);
        }
        for (int gb = beg + 32; gb < end; gb += 32) {
            int e = gb + lane;
            int s = 0; float w = 0.f;
            if (e < end) {
                s = __ldg(&g_csr2[e]);
                float lg = __ldg(&g_asrc[s]) + adst_v;
                lg = (lg > 0.f) ? lg : NEG_SLOPE * lg;
                w = __expf(lg);
            }
            int cnt = min(32, end - gb);
#pragma unroll 4
            for (int j = 0; j < cnt; j++) {
                float wj = __shfl_sync(FULL, w, j);
                int   sj = __shfl_sync(FULL, s, j);
                float4 hv = *(const float4*)&h[sj * DH + lane * 4];
                ssum += wj;
                ax = fmaf(wj, hv.x, ax);
                ay = fmaf(wj, hv.y, ay);
                az = fmaf(wj, hv.z, az);
                aw = fmaf(wj, hv.w, aw);
            }
        }

        float inv = 1.f / (ssum + 1e-16f);
        float4 b = *(const float4*)&bias[lane * 4];
        float ox = fmaxf(fmaf(ax, inv, b.x), 0.f);
        float oy = fmaxf(fmaf(ay, inv, b.y), 0.f);
        float oz = fmaxf(fmaf(az, inv, b.z), 0.f);
        float ow = fmaxf(fmaf(aw, inv, b.w), 0.f);

        if (POOL) {
            int gi = batch[node];
            gi = (gi < 0) ? 0 : ((gi >= NG) ? NG - 1 : gi);
            if (gi == gmin) {
                float* p = &sbuf[lane * 4];
                atomicAdd(p + 0, ox);
                atomicAdd(p + 1, oy);
                atomicAdd(p + 2, oz);
                atomicAdd(p + 3, ow);
            } else {
                float* p = &g_pooled[gi * DH + lane * 4];
                atomicAdd(p + 0, ox);
                atomicAdd(p + 1, oy);
                atomicAdd(p + 2, oz);
                atomicAdd(p + 3, ow);
            }
        } else {
            __nv_bfloat162 p0, p1;
            p0.x = __float2bfloat16(ox); p0.y = __float2bfloat16(oy);
            p1.x = __float2bfloat16(oz); p1.y = __float2bfloat16(ow);
            *(__nv_bfloat162*)&out[node * DH + lane * 4]     = p0;
            *(__nv_bfloat162*)&out[node * DH + lane * 4 + 2] = p1;
        }
    }

    if (POOL) {
        __syncthreads();
        if (tid < DH) {
            float v = sbuf[tid];
            if (v != 0.f) atomicAdd(&g_pooled[gmin * DH + tid], v);
        }
    }
}

// ---------------- fused FFN head: one block per graph --------------------
__global__ __launch_bounds__(512)
void ffn_kernel(const float* __restrict__ Wf1, const float* __restrict__ bf1,
                const float* __restrict__ Wf2, const float* __restrict__ bf2,
                const float* __restrict__ Wf3, const float* __restrict__ bf3,
                float* __restrict__ out) {
    __shared__ float pz[DH];
    __shared__ float z1[DF];
    __shared__ float z2[DF];
    const int g = blockIdx.x;
    const int t = threadIdx.x;

    if (t < DH) {
        float c = (float)g_cnt[g];
        pz[t] = g_pooled[g * DH + t] / fmaxf(c, 1.f);
    }
    __syncthreads();

    {
        float acc = bf1[t];
#pragma unroll 8
        for (int k = 0; k < DH; k++)
            acc = fmaf(pz[k], Wf1[k * DF + t], acc);
        z1[t] = fmaxf(acc, 0.f);
    }
    __syncthreads();

    {
        float acc = bf2[t];
#pragma unroll 8
        for (int k = 0; k < DF; k++)
            acc = fmaf(z1[k], Wf2[k * DF + t], acc);
        z2[t] = fmaxf(acc, 0.f);
    }
    __syncthreads();

    if (t < NCLS * 16) {
        int c = t >> 4, p = t & 15;
        float acc = 0.f;
        for (int k = p * 32; k < p * 32 + 32; k++)
            acc = fmaf(z2[k], Wf3[k * NCLS + c], acc);
#pragma unroll
        for (int o = 8; o > 0; o >>= 1)
            acc += __shfl_xor_sync(0xffffffffu, acc, o);
        if (p == 0) out[g * NCLS + c] = acc + bf3[c];
    }
}

// ---------------- launch ----------------
extern "C" void kernel_launch(void* const* d_in, const int* in_sizes, int n_in,
                              void* d_out, int out_size) {
    const float* x     = (const float*)d_in[0];
    const int*   ei    = (const int*)d_in[1];
    const int*   batch = (const int*)d_in[2];
    const float* W1  = (const float*)d_in[3];
    const float* as1 = (const float*)d_in[4];
    const float* ad1 = (const float*)d_in[5];
    const float* b1  = (const float*)d_in[6];
    const float* W2  = (const float*)d_in[7];
    const float* as2 = (const float*)d_in[8];
    const float* ad2 = (const float*)d_in[9];
    const float* b2  = (const float*)d_in[10];
    const float* W3  = (const float*)d_in[11];
    const float* as3 = (const float*)d_in[12];
    const float* ad3 = (const float*)d_in[13];
    const float* b3  = (const float*)d_in[14];
    const float* Wf1 = (const float*)d_in[15];
    const float* bf1 = (const float*)d_in[16];
    const float* Wf2 = (const float*)d_in[17];
    const float* bf2 = (const float*)d_in[18];
    const float* Wf3 = (const float*)d_in[19];
    const float* bf3 = (const float*)d_in[20];
    float* out = (float*)d_out;

    float* hT;            cudaGetSymbolAddress((void**)&hT, g_hT);
    __nv_bfloat16* bufA;  cudaGetSymbolAddress((void**)&bufA, g_bufA);
    __nv_bfloat16* bufB;  cudaGetSymbolAddress((void**)&bufB, g_bufB);
    __nv_bfloat16* Wb;    cudaGetSymbolAddress((void**)&Wb, g_Wb);

    // side stream + events + smem attributes, set on first (uncaptured) call
    static cudaStream_t s2 = nullptr;
    static cudaEvent_t evFork = nullptr, evJoin = nullptr;
    if (!s2) {
        cudaStreamCreateWithFlags(&s2, cudaStreamNonBlocking);
        cudaEventCreateWithFlags(&evFork, cudaEventDisableTiming);
        cudaEventCreateWithFlags(&evJoin, cudaEventDisableTiming);
        cudaFuncSetAttribute(gemm_bf16_kernel<float>,
                             cudaFuncAttributeMaxDynamicSharedMemorySize, SMEM_BYTES);
        cudaFuncSetAttribute(gemm_bf16_kernel<__nv_bfloat16>,
                             cudaFuncAttributeMaxDynamicSharedMemorySize, SMEM_BYTES);
    }

    const int gemm_blocks = (NN + 127) / 128;
    const int warp_blocks = (NN * 32 + 255) / 256;

    // fork: CSR build on s2, concurrent with cvtw + gemm layer 1
    cudaEventRecord(evFork, 0);
    cudaStreamWaitEvent(s2, evFork, 0);
    zero_kernel<<<(NN + 255) / 256, 256, 0, s2>>>();
    scatter_kernel<<<(ETOT + 255) / 256, 256, 0, s2>>>(ei, batch);
    cudaEventRecord(evJoin, s2);

    cvtw_kernel<<<(3 * DH * DH + 255) / 256, 256>>>(W1, W2, W3);
    // layer 1 GEMM consumes fp32 x directly (fused conversion)
    gemm_bf16_kernel<float><<<gemm_blocks, 256, SMEM_BYTES>>>(x, Wb, hT, NN, as1, ad1);

    // join: aggregation needs the CSR
    cudaStreamWaitEvent(0, evJoin, 0);
    aggregate_kernel<false><<<warp_blocks, 256>>>(hT, b1, bufA, batch);
    // layer 2
    gemm_bf16_kernel<__nv_bfloat16><<<gemm_blocks, 256, SMEM_BYTES>>>(bufA, Wb + DH * DH, hT, NN, as2, ad2);
    aggregate_kernel<false><<<warp_blocks, 256>>>(hT, b2, bufB, batch);
    // layer 3 -> pooled
    gemm_bf16_kernel<__nv_bfloat16><<<gemm_blocks, 256, SMEM_BYTES>>>(bufB, Wb + 2 * DH * DH, hT, NN, as3, ad3);
    aggregate_kernel<true><<<warp_blocks, 256>>>(hT, b3, bufA, batch);

    // fused head
    ffn_kernel<<<NG, 512>>>(Wf1, bf1, Wf2, bf2, Wf3, bf3, out);
}